// round 1
// baseline (speedup 1.0000x reference)
#include <cuda_runtime.h>
#include <math.h>

#define T_TOK 8192
#define D_DIM 1024
#define F_DIM 4096
#define E_EXP 8

// ---------------- scratch (static device globals; no allocations) ----------
__device__ int   g_cnt[E_EXP];
__device__ int   g_off[E_EXP];
__device__ int   g_tok[E_EXP * T_TOK];
__device__ float g_wt [E_EXP * T_TOK];
// total assignments = T_TOK * TOP_K = 16384 rows of F_DIM floats = 256 MB
__device__ float g_h  [16384 * (size_t)F_DIM];

// ---------------- init: zero counters + zero the 'out' region --------------
__global__ void k_init(float4* __restrict__ out4) {
    int i = blockIdx.x * blockDim.x + threadIdx.x;
    if (i < E_EXP) g_cnt[i] = 0;
    const size_t n4 = (size_t)T_TOK * D_DIM / 4;
    float4 z = make_float4(0.f, 0.f, 0.f, 0.f);
    for (size_t j = i; j < n4; j += (size_t)gridDim.x * blockDim.x)
        out4[j] = z;
}

// ---------------- gating: logits -> softmax -> probs + top2 routing --------
__global__ void k_gate(const float* __restrict__ x, const float* __restrict__ gw,
                       float* __restrict__ probs_out) {
    int warp = (blockIdx.x * blockDim.x + threadIdx.x) >> 5;
    int lane = threadIdx.x & 31;
    if (warp >= T_TOK) return;
    const float* xr = x + (size_t)warp * D_DIM;
    float acc[E_EXP];
#pragma unroll
    for (int e = 0; e < E_EXP; e++) acc[e] = 0.f;

    for (int k = lane * 4; k < D_DIM; k += 32 * 4) {
        float4 xv = *(const float4*)(xr + k);
#pragma unroll
        for (int e = 0; e < E_EXP; e++) {
            float4 wv = *(const float4*)(gw + (size_t)e * D_DIM + k);
            acc[e] += xv.x * wv.x + xv.y * wv.y + xv.z * wv.z + xv.w * wv.w;
        }
    }
#pragma unroll
    for (int e = 0; e < E_EXP; e++)
#pragma unroll
        for (int o = 16; o > 0; o >>= 1)
            acc[e] += __shfl_xor_sync(0xffffffffu, acc[e], o);

    if (lane == 0) {
        float mx = acc[0];
#pragma unroll
        for (int e = 1; e < E_EXP; e++) mx = fmaxf(mx, acc[e]);
        float p[E_EXP]; float s = 0.f;
#pragma unroll
        for (int e = 0; e < E_EXP; e++) { p[e] = expf(acc[e] - mx); s += p[e]; }
        float inv = 1.f / s;
#pragma unroll
        for (int e = 0; e < E_EXP; e++) {
            p[e] *= inv;
            probs_out[(size_t)warp * E_EXP + e] = p[e];
        }
        // top-2 (lowest index wins ties, matching jax.lax.top_k)
        int i0 = 0;
#pragma unroll
        for (int e = 1; e < E_EXP; e++) if (p[e] > p[i0]) i0 = e;
        int i1 = (i0 == 0) ? 1 : 0;
#pragma unroll
        for (int e = 0; e < E_EXP; e++)
            if (e != i0 && p[e] > p[i1]) i1 = e;
        float denom = p[i0] + p[i1] + 1e-9f;
        float w0 = p[i0] / denom, w1 = p[i1] / denom;
        int s0 = atomicAdd(&g_cnt[i0], 1);
        g_tok[i0 * T_TOK + s0] = warp; g_wt[i0 * T_TOK + s0] = w0;
        int s1 = atomicAdd(&g_cnt[i1], 1);
        g_tok[i1 * T_TOK + s1] = warp; g_wt[i1 * T_TOK + s1] = w1;
    }
}

// ---------------- prefix over 8 counters ------------------------------------
__global__ void k_prefix() {
    if (threadIdx.x == 0) {
        int run = 0;
#pragma unroll
        for (int e = 0; e < E_EXP; e++) { g_off[e] = run; run += g_cnt[e]; }
    }
}

// ---------------- GEMM1: h = gelu(X[tok] @ W1e^T + b1e) --------------------
// tile 128x128x16, 256 threads, 8x8 per thread
__global__ __launch_bounds__(256) void k_fc1(const float* __restrict__ x,
                                             const float* __restrict__ w1,
                                             const float* __restrict__ b1) {
    const int e = blockIdx.z;
    const int cnt = g_cnt[e];
    const int m0 = blockIdx.y * 128;
    if (m0 >= cnt) return;

    __shared__ float As[16][132];
    __shared__ float Bs[16][132];
    __shared__ int   toks[128];

    const int tid = threadIdx.x;
    if (tid < 128) {
        int m = m0 + tid;
        toks[tid] = g_tok[e * T_TOK + min(m, cnt - 1)];
    }
    __syncthreads();

    const float* Bp = w1 + (size_t)e * F_DIM * D_DIM + (size_t)(blockIdx.x * 128) * D_DIM;
    const int tx = tid & 15, ty = tid >> 4;

    float c[8][8];
#pragma unroll
    for (int i = 0; i < 8; i++)
#pragma unroll
        for (int j = 0; j < 8; j++) c[i][j] = 0.f;

    for (int kt = 0; kt < D_DIM; kt += 16) {
#pragma unroll
        for (int l = 0; l < 2; l++) {
            int id  = tid + 256 * l;
            int row = id >> 2, kq = id & 3;
            float4 av = *(const float4*)(x + (size_t)toks[row] * D_DIM + kt + kq * 4);
            As[kq * 4 + 0][row] = av.x; As[kq * 4 + 1][row] = av.y;
            As[kq * 4 + 2][row] = av.z; As[kq * 4 + 3][row] = av.w;
            float4 bv = *(const float4*)(Bp + (size_t)row * D_DIM + kt + kq * 4);
            Bs[kq * 4 + 0][row] = bv.x; Bs[kq * 4 + 1][row] = bv.y;
            Bs[kq * 4 + 2][row] = bv.z; Bs[kq * 4 + 3][row] = bv.w;
        }
        __syncthreads();
#pragma unroll
        for (int k = 0; k < 16; k++) {
            float a[8], b[8];
            *(float4*)(a)     = *(const float4*)&As[k][ty * 8];
            *(float4*)(a + 4) = *(const float4*)&As[k][ty * 8 + 4];
            *(float4*)(b)     = *(const float4*)&Bs[k][tx * 8];
            *(float4*)(b + 4) = *(const float4*)&Bs[k][tx * 8 + 4];
#pragma unroll
            for (int i = 0; i < 8; i++)
#pragma unroll
                for (int j = 0; j < 8; j++) c[i][j] += a[i] * b[j];
        }
        __syncthreads();
    }

    const int hbase = g_off[e] + m0;
#pragma unroll
    for (int i = 0; i < 8; i++) {
        int r = ty * 8 + i;
        if (m0 + r >= cnt) continue;
        size_t hrow = (size_t)(hbase + r) * F_DIM;
#pragma unroll
        for (int j = 0; j < 8; j++) {
            int n = blockIdx.x * 128 + tx * 8 + j;
            float v = c[i][j] + b1[e * F_DIM + n];
            v = 0.5f * v * (1.f + erff(v * 0.70710678118654752f));  // exact gelu
            g_h[hrow + n] = v;
        }
    }
}

// ---------------- GEMM2: out[tok] += w * (h @ W2e^T + b2e) ------------------
__global__ __launch_bounds__(256) void k_fc2(const float* __restrict__ w2,
                                             const float* __restrict__ b2,
                                             float* __restrict__ out) {
    const int e = blockIdx.z;
    const int cnt = g_cnt[e];
    const int m0 = blockIdx.y * 128;
    if (m0 >= cnt) return;

    __shared__ float As[16][132];
    __shared__ float Bs[16][132];

    const int tid = threadIdx.x;
    const int tx = tid & 15, ty = tid >> 4;
    const float* Ap = g_h + (size_t)g_off[e] * F_DIM;
    const float* Bp = w2 + (size_t)e * D_DIM * F_DIM + (size_t)(blockIdx.x * 128) * F_DIM;

    float c[8][8];
#pragma unroll
    for (int i = 0; i < 8; i++)
#pragma unroll
        for (int j = 0; j < 8; j++) c[i][j] = 0.f;

    for (int kt = 0; kt < F_DIM; kt += 16) {
#pragma unroll
        for (int l = 0; l < 2; l++) {
            int id  = tid + 256 * l;
            int row = id >> 2, kq = id & 3;
            int arow = min(m0 + row, cnt - 1);
            float4 av = *(const float4*)(Ap + (size_t)arow * F_DIM + kt + kq * 4);
            As[kq * 4 + 0][row] = av.x; As[kq * 4 + 1][row] = av.y;
            As[kq * 4 + 2][row] = av.z; As[kq * 4 + 3][row] = av.w;
            float4 bv = *(const float4*)(Bp + (size_t)row * F_DIM + kt + kq * 4);
            Bs[kq * 4 + 0][row] = bv.x; Bs[kq * 4 + 1][row] = bv.y;
            Bs[kq * 4 + 2][row] = bv.z; Bs[kq * 4 + 3][row] = bv.w;
        }
        __syncthreads();
#pragma unroll
        for (int k = 0; k < 16; k++) {
            float a[8], b[8];
            *(float4*)(a)     = *(const float4*)&As[k][ty * 8];
            *(float4*)(a + 4) = *(const float4*)&As[k][ty * 8 + 4];
            *(float4*)(b)     = *(const float4*)&Bs[k][tx * 8];
            *(float4*)(b + 4) = *(const float4*)&Bs[k][tx * 8 + 4];
#pragma unroll
            for (int i = 0; i < 8; i++)
#pragma unroll
                for (int j = 0; j < 8; j++) c[i][j] += a[i] * b[j];
        }
        __syncthreads();
    }

#pragma unroll
    for (int i = 0; i < 8; i++) {
        int r = ty * 8 + i;
        if (m0 + r >= cnt) continue;
        int t = g_tok[e * T_TOK + m0 + r];
        float w = g_wt[e * T_TOK + m0 + r];
        size_t orow = (size_t)t * D_DIM;
#pragma unroll
        for (int j = 0; j < 8; j++) {
            int n = blockIdx.x * 128 + tx * 8 + j;
            float v = w * (c[i][j] + b2[e * D_DIM + n]);
            atomicAdd(&out[orow + n], v);  // exactly 2 adds/elem onto 0 -> deterministic
        }
    }
}

// ---------------- launch -----------------------------------------------------
extern "C" void kernel_launch(void* const* d_in, const int* in_sizes, int n_in,
                              void* d_out, int out_size) {
    const float* x  = (const float*)d_in[0];
    const float* gw = (const float*)d_in[1];
    const float* w1 = (const float*)d_in[2];
    const float* b1 = (const float*)d_in[3];
    const float* w2 = (const float*)d_in[4];
    const float* b2 = (const float*)d_in[5];
    float* out   = (float*)d_out;
    float* probs = out + (size_t)T_TOK * D_DIM;

    k_init<<<512, 256>>>((float4*)out);
    k_gate<<<T_TOK / 8, 256>>>(x, gw, probs);
    k_prefix<<<1, 32>>>();
    k_fc1<<<dim3(F_DIM / 128, T_TOK / 128, E_EXP), 256>>>(x, w1, b1);
    k_fc2<<<dim3(D_DIM / 128, T_TOK / 128, E_EXP), 256>>>(w2, b2, out);
}

// round 3
// speedup vs baseline: 2.4765x; 2.4765x over previous
#include <cuda_runtime.h>
#include <cuda_bf16.h>
#include <math.h>
#include <stdint.h>

#define T_TOK 8192
#define D_DIM 1024
#define F_DIM 4096
#define E_EXP 8

// ---------------- scratch (static device globals; no allocations) ----------
__device__ int   g_cnt[E_EXP];
__device__ int   g_off[E_EXP];
__device__ int   g_tok[E_EXP * T_TOK];
__device__ float g_wt [E_EXP * T_TOK];

__device__ __nv_bfloat16 g_xhi [(size_t)T_TOK * D_DIM];
__device__ __nv_bfloat16 g_xlo [(size_t)T_TOK * D_DIM];
__device__ __nv_bfloat16 g_w1hi[(size_t)E_EXP * F_DIM * D_DIM];
__device__ __nv_bfloat16 g_w1lo[(size_t)E_EXP * F_DIM * D_DIM];
__device__ __nv_bfloat16 g_w2hi[(size_t)E_EXP * D_DIM * F_DIM];
__device__ __nv_bfloat16 g_w2lo[(size_t)E_EXP * D_DIM * F_DIM];
__device__ __nv_bfloat16 g_hhi [(size_t)2 * T_TOK * F_DIM];
__device__ __nv_bfloat16 g_hlo [(size_t)2 * T_TOK * F_DIM];

// ---------------- PTX helpers (sm_80+ features only; no 'a'-gated ops) -----
__device__ __forceinline__ uint32_t smem_u32(const void* p) {
    uint32_t a;
    asm("{ .reg .u64 t; cvta.to.shared.u64 t, %1; cvt.u32.u64 %0, t; }" : "=r"(a) : "l"(p));
    return a;
}
#define CP16(dst, src) asm volatile("cp.async.ca.shared.global [%0], [%1], 16;" :: "r"(dst), "l"(src) : "memory")
#define CP_COMMIT()    asm volatile("cp.async.commit_group;" ::: "memory")
#define CP_WAIT(n)     asm volatile("cp.async.wait_group %0;" :: "n"(n) : "memory")
#define LDX4(r, a)                                                             \
    asm volatile("ldmatrix.sync.aligned.m8n8.x4.shared.b16 {%0,%1,%2,%3}, [%4];" \
        : "=r"((r)[0]), "=r"((r)[1]), "=r"((r)[2]), "=r"((r)[3]) : "r"(a))
#define MMA16(d, a, b0, b1)                                                    \
    asm volatile("mma.sync.aligned.m16n8k16.row.col.f32.bf16.bf16.f32 "        \
        "{%0,%1,%2,%3},{%4,%5,%6,%7},{%8,%9},{%0,%1,%2,%3};"                   \
        : "+f"((d)[0]), "+f"((d)[1]), "+f"((d)[2]), "+f"((d)[3])               \
        : "r"((a)[0]), "r"((a)[1]), "r"((a)[2]), "r"((a)[3]), "r"(b0), "r"(b1))

__device__ __forceinline__ uint32_t pack_bf(__nv_bfloat16 a, __nv_bfloat16 b) {
    return ((uint32_t)__bfloat16_as_ushort(b) << 16) | __bfloat16_as_ushort(a);
}

// SMEM: [0,512) toks, [512,1024) bias, [1024,1536) wts, [2048, 2048+2*40960) stages
// stage layout: Ahi @0, Alo @10240, Bhi @20480, Blo @30720; row pitch 80B (32 bf16 + pad)
#define SM_STAGE 2048
#define STG_SZ   40960
#define SMEM_DYN (SM_STAGE + 2 * STG_SZ)

// ---------------- init ------------------------------------------------------
__global__ void k_init(float4* __restrict__ out4) {
    int i = blockIdx.x * blockDim.x + threadIdx.x;
    if (i < E_EXP) g_cnt[i] = 0;
    const size_t n4 = (size_t)T_TOK * D_DIM / 4;
    float4 z = make_float4(0.f, 0.f, 0.f, 0.f);
    for (size_t j = i; j < n4; j += (size_t)gridDim.x * blockDim.x) out4[j] = z;
}

// ---------------- split fp32 -> bf16 hi/lo ----------------------------------
__device__ __forceinline__ void split4(__nv_bfloat16* hi, __nv_bfloat16* lo,
                                       const float* s, size_t i) {
    float4 f = ((const float4*)s)[i];
    __nv_bfloat16 h0 = __float2bfloat16(f.x), h1 = __float2bfloat16(f.y);
    __nv_bfloat16 h2 = __float2bfloat16(f.z), h3 = __float2bfloat16(f.w);
    __nv_bfloat16 l0 = __float2bfloat16(f.x - __bfloat162float(h0));
    __nv_bfloat16 l1 = __float2bfloat16(f.y - __bfloat162float(h1));
    __nv_bfloat16 l2 = __float2bfloat16(f.z - __bfloat162float(h2));
    __nv_bfloat16 l3 = __float2bfloat16(f.w - __bfloat162float(h3));
    ((uint2*)hi)[i] = make_uint2(pack_bf(h0, h1), pack_bf(h2, h3));
    ((uint2*)lo)[i] = make_uint2(pack_bf(l0, l1), pack_bf(l2, l3));
}
__global__ void k_split(const float* __restrict__ x, const float* __restrict__ w1,
                        const float* __restrict__ w2) {
    size_t stride = (size_t)gridDim.x * blockDim.x;
    size_t i0 = (size_t)blockIdx.x * blockDim.x + threadIdx.x;
    const size_t nx4 = (size_t)T_TOK * D_DIM / 4;
    const size_t nw4 = (size_t)E_EXP * F_DIM * D_DIM / 4;
    for (size_t i = i0; i < nx4; i += stride) split4(g_xhi, g_xlo, x, i);
    for (size_t i = i0; i < nw4; i += stride) split4(g_w1hi, g_w1lo, w1, i);
    for (size_t i = i0; i < nw4; i += stride) split4(g_w2hi, g_w2lo, w2, i);
}

// ---------------- gating (validated in R1) ----------------------------------
__global__ void k_gate(const float* __restrict__ x, const float* __restrict__ gw,
                       float* __restrict__ probs_out) {
    int warp = (blockIdx.x * blockDim.x + threadIdx.x) >> 5;
    int lane = threadIdx.x & 31;
    if (warp >= T_TOK) return;
    const float* xr = x + (size_t)warp * D_DIM;
    float acc[E_EXP];
#pragma unroll
    for (int e = 0; e < E_EXP; e++) acc[e] = 0.f;
    for (int k = lane * 4; k < D_DIM; k += 128) {
        float4 xv = *(const float4*)(xr + k);
#pragma unroll
        for (int e = 0; e < E_EXP; e++) {
            float4 wv = *(const float4*)(gw + (size_t)e * D_DIM + k);
            acc[e] += xv.x * wv.x + xv.y * wv.y + xv.z * wv.z + xv.w * wv.w;
        }
    }
#pragma unroll
    for (int e = 0; e < E_EXP; e++)
#pragma unroll
        for (int o = 16; o > 0; o >>= 1) acc[e] += __shfl_xor_sync(0xffffffffu, acc[e], o);
    if (lane == 0) {
        float mx = acc[0];
#pragma unroll
        for (int e = 1; e < E_EXP; e++) mx = fmaxf(mx, acc[e]);
        float p[E_EXP], s = 0.f;
#pragma unroll
        for (int e = 0; e < E_EXP; e++) { p[e] = expf(acc[e] - mx); s += p[e]; }
        float inv = 1.f / s;
#pragma unroll
        for (int e = 0; e < E_EXP; e++) {
            p[e] *= inv;
            probs_out[(size_t)warp * E_EXP + e] = p[e];
        }
        int i0 = 0;
#pragma unroll
        for (int e = 1; e < E_EXP; e++) if (p[e] > p[i0]) i0 = e;
        int i1 = (i0 == 0) ? 1 : 0;
#pragma unroll
        for (int e = 0; e < E_EXP; e++) if (e != i0 && p[e] > p[i1]) i1 = e;
        float denom = p[i0] + p[i1] + 1e-9f;
        int s0 = atomicAdd(&g_cnt[i0], 1);
        g_tok[i0 * T_TOK + s0] = warp; g_wt[i0 * T_TOK + s0] = p[i0] / denom;
        int s1 = atomicAdd(&g_cnt[i1], 1);
        g_tok[i1 * T_TOK + s1] = warp; g_wt[i1 * T_TOK + s1] = p[i1] / denom;
    }
}
__global__ void k_prefix() {
    if (threadIdx.x == 0) {
        int run = 0;
#pragma unroll
        for (int e = 0; e < E_EXP; e++) { g_off[e] = run; run += g_cnt[e]; }
    }
}

// ---------------- shared GEMM chunk: 128x128x32, 3-term bf16 split ----------
#define CHUNK(so)                                                              \
    _Pragma("unroll") for (int kk = 0; kk < 2; ++kk) {                         \
        uint32_t Ah0[4], Ah1[4], Al0[4], Al1[4];                               \
        LDX4(Ah0, aa0 + (so) + kk * 32);                                       \
        LDX4(Ah1, aa1 + (so) + kk * 32);                                       \
        LDX4(Al0, aa0 + (so) + 10240 + kk * 32);                               \
        LDX4(Al1, aa1 + (so) + 10240 + kk * 32);                               \
        _Pragma("unroll") for (int g = 0; g < 4; ++g) {                        \
            uint32_t Bh[4], Bl[4];                                             \
            LDX4(Bh, bbv[g] + (so) + kk * 32);                                 \
            LDX4(Bl, bbv[g] + (so) + 10240 + kk * 32);                         \
            MMA16(acc[0][2 * g],     Ah0, Bh[0], Bh[1]);                       \
            MMA16(acc[0][2 * g],     Ah0, Bl[0], Bl[1]);                       \
            MMA16(acc[0][2 * g],     Al0, Bh[0], Bh[1]);                       \
            MMA16(acc[1][2 * g],     Ah1, Bh[0], Bh[1]);                       \
            MMA16(acc[1][2 * g],     Ah1, Bl[0], Bl[1]);                       \
            MMA16(acc[1][2 * g],     Al1, Bh[0], Bh[1]);                       \
            MMA16(acc[0][2 * g + 1], Ah0, Bh[2], Bh[3]);                       \
            MMA16(acc[0][2 * g + 1], Ah0, Bl[2], Bl[3]);                       \
            MMA16(acc[0][2 * g + 1], Al0, Bh[2], Bh[3]);                       \
            MMA16(acc[1][2 * g + 1], Ah1, Bh[2], Bh[3]);                       \
            MMA16(acc[1][2 * g + 1], Ah1, Bl[2], Bl[3]);                       \
            MMA16(acc[1][2 * g + 1], Al1, Bh[2], Bh[3]);                       \
        }                                                                      \
    }

#define LDM_SETUP()                                                            \
    const int lane = tid & 31, wid = tid >> 5;                                 \
    const int wm = (wid & 3) * 32, wn = (wid >> 2) * 64;                       \
    const uint32_t aa0 = sb + SM_STAGE +                                       \
        (wm + (lane & 7) + ((lane >> 3) & 1) * 8) * 80 + ((lane >> 4) & 1) * 16; \
    const uint32_t aa1 = aa0 + 16 * 80;                                        \
    uint32_t bbv[4];                                                           \
    _Pragma("unroll") for (int g = 0; g < 4; ++g)                              \
        bbv[g] = sb + SM_STAGE + 20480 +                                       \
            (wn + g * 16 + (lane & 7) + ((lane >> 4) & 1) * 8) * 80 +          \
            ((lane >> 3) & 1) * 16;

// ---------------- fc1: h = gelu(X[gather] @ W1e^T + b1) -> bf16 hi/lo -------
__global__ __launch_bounds__(256, 1) void k_fc1_m(const float* __restrict__ b1) {
    const int e = blockIdx.z;
    const int cnt = g_cnt[e];
    const int m0 = blockIdx.y * 128;
    if (m0 >= cnt) return;
    const int n0 = blockIdx.x * 128;

    extern __shared__ __align__(128) char smp[];
    const uint32_t sb = smem_u32(smp);
    int*   toks_s = (int*)smp;
    float* bias_s = (float*)(smp + 512);
    const int tid = threadIdx.x;
    if (tid < 128) {
        toks_s[tid] = g_tok[e * T_TOK + min(m0 + tid, cnt - 1)];
        bias_s[tid] = b1[e * F_DIM + n0 + tid];
    }
    __syncthreads();

    // staging: thread -> quad q, rows r0 / r0+64 of each of 4 arrays
    const int q = tid & 3, r0 = tid >> 2, r1 = r0 + 64;
    const uint32_t d0 = sb + SM_STAGE + r0 * 80 + q * 16;
    const uint32_t d1 = sb + SM_STAGE + r1 * 80 + q * 16;
    const uint32_t a0off = (uint32_t)toks_s[r0] * (D_DIM * 2) + q * 16;
    const uint32_t a1off = (uint32_t)toks_s[r1] * (D_DIM * 2) + q * 16;
    const char* xhi = (const char*)g_xhi;
    const char* xlo = (const char*)g_xlo;
    const char* bh0 = (const char*)(g_w1hi + ((size_t)e * F_DIM + n0 + r0) * D_DIM) + q * 16;
    const char* bh1 = (const char*)(g_w1hi + ((size_t)e * F_DIM + n0 + r1) * D_DIM) + q * 16;
    const char* bl0 = (const char*)(g_w1lo + ((size_t)e * F_DIM + n0 + r0) * D_DIM) + q * 16;
    const char* bl1 = (const char*)(g_w1lo + ((size_t)e * F_DIM + n0 + r1) * D_DIM) + q * 16;

#define STAGE1(c, so) { const uint32_t ko = (uint32_t)(c) * 64;                \
    CP16(d0 + (so),         xhi + a0off + ko);                                 \
    CP16(d1 + (so),         xhi + a1off + ko);                                 \
    CP16(d0 + (so) + 10240, xlo + a0off + ko);                                 \
    CP16(d1 + (so) + 10240, xlo + a1off + ko);                                 \
    CP16(d0 + (so) + 20480, bh0 + ko);                                         \
    CP16(d1 + (so) + 20480, bh1 + ko);                                         \
    CP16(d0 + (so) + 30720, bl0 + ko);                                         \
    CP16(d1 + (so) + 30720, bl1 + ko);                                         \
    CP_COMMIT(); }

    LDM_SETUP();
    float acc[2][8][4];
#pragma unroll
    for (int i = 0; i < 2; i++)
#pragma unroll
        for (int j = 0; j < 8; j++)
#pragma unroll
            for (int k = 0; k < 4; k++) acc[i][j][k] = 0.f;

    STAGE1(0, 0);
    const int NC = D_DIM / 32;  // 32
    for (int c = 0; c < NC; ++c) {
        const uint32_t so = (uint32_t)(c & 1) * STG_SZ;
        if (c + 1 < NC) { STAGE1(c + 1, (uint32_t)((c + 1) & 1) * STG_SZ); CP_WAIT(1); }
        else            { CP_WAIT(0); }
        __syncthreads();
        CHUNK(so);
        __syncthreads();
    }

    // arch probe: if a compute_103a pass exists, this shows up in SASS
#if defined(__CUDA_ARCH_FEAT_SM103_ALL) || defined(__CUDA_ARCH_FEAT_SM100_ALL)
    if (cnt == -1) asm volatile("tcgen05.fence::before_thread_sync;");
#endif

    // epilogue: bias + exact gelu -> split bf16 -> g_hhi/g_hlo
    const int gid2 = lane >> 2, tg = lane & 3;
    const int hbase = g_off[e] + m0;
    uint32_t* ghi = (uint32_t*)g_hhi;
    uint32_t* glo = (uint32_t*)g_hlo;
#pragma unroll
    for (int mi = 0; mi < 2; ++mi)
#pragma unroll
        for (int nt = 0; nt < 8; ++nt) {
            const int n = wn + nt * 8 + tg * 2;
            const float bv0 = bias_s[n], bv1 = bias_s[n + 1];
#pragma unroll
            for (int h = 0; h < 2; ++h) {
                const int m = wm + mi * 16 + gid2 + h * 8;
                if (m0 + m < cnt) {
                    float v0 = acc[mi][nt][2 * h + 0] + bv0;
                    float v1 = acc[mi][nt][2 * h + 1] + bv1;
                    v0 = 0.5f * v0 * (1.f + erff(v0 * 0.7071067811865476f));
                    v1 = 0.5f * v1 * (1.f + erff(v1 * 0.7071067811865476f));
                    __nv_bfloat16 h0 = __float2bfloat16(v0), h1 = __float2bfloat16(v1);
                    __nv_bfloat16 l0 = __float2bfloat16(v0 - __bfloat162float(h0));
                    __nv_bfloat16 l1 = __float2bfloat16(v1 - __bfloat162float(h1));
                    size_t idx = (size_t)(hbase + m) * (F_DIM / 2) + (size_t)(n0 + n) / 2;
                    ghi[idx] = pack_bf(h0, h1);
                    glo[idx] = pack_bf(l0, l1);
                }
            }
        }
}

// ---------------- fc2: out[tok] += w * (h @ W2e^T + b2) ---------------------
__global__ __launch_bounds__(256, 1) void k_fc2_m(const float* __restrict__ b2,
                                                  float* __restrict__ out) {
    const int e = blockIdx.z;
    const int cnt = g_cnt[e];
    const int m0 = blockIdx.y * 128;
    if (m0 >= cnt) return;
    const int n0 = blockIdx.x * 128;

    extern __shared__ __align__(128) char smp[];
    const uint32_t sb = smem_u32(smp);
    int*   toks_s = (int*)smp;
    float* bias_s = (float*)(smp + 512);
    float* wts_s  = (float*)(smp + 1024);
    const int tid = threadIdx.x;
    if (tid < 128) {
        const int slot = min(m0 + tid, cnt - 1);
        toks_s[tid] = g_tok[e * T_TOK + slot];
        wts_s[tid]  = g_wt [e * T_TOK + slot];
        bias_s[tid] = b2[e * D_DIM + n0 + tid];
    }
    __syncthreads();

    const int q = tid & 3, r0 = tid >> 2, r1 = r0 + 64;
    const uint32_t d0 = sb + SM_STAGE + r0 * 80 + q * 16;
    const uint32_t d1 = sb + SM_STAGE + r1 * 80 + q * 16;
    const uint32_t slot0 = (uint32_t)(g_off[e] + min(m0 + r0, cnt - 1));
    const uint32_t slot1 = (uint32_t)(g_off[e] + min(m0 + r1, cnt - 1));
    const char* ah0 = (const char*)(g_hhi + (size_t)slot0 * F_DIM) + q * 16;
    const char* ah1 = (const char*)(g_hhi + (size_t)slot1 * F_DIM) + q * 16;
    const char* al0 = (const char*)(g_hlo + (size_t)slot0 * F_DIM) + q * 16;
    const char* al1 = (const char*)(g_hlo + (size_t)slot1 * F_DIM) + q * 16;
    const char* bh0 = (const char*)(g_w2hi + ((size_t)e * D_DIM + n0 + r0) * F_DIM) + q * 16;
    const char* bh1 = (const char*)(g_w2hi + ((size_t)e * D_DIM + n0 + r1) * F_DIM) + q * 16;
    const char* bl0 = (const char*)(g_w2lo + ((size_t)e * D_DIM + n0 + r0) * F_DIM) + q * 16;
    const char* bl1 = (const char*)(g_w2lo + ((size_t)e * D_DIM + n0 + r1) * F_DIM) + q * 16;

#define STAGE2(c, so) { const uint32_t ko = (uint32_t)(c) * 64;                \
    CP16(d0 + (so),         ah0 + ko);                                         \
    CP16(d1 + (so),         ah1 + ko);                                         \
    CP16(d0 + (so) + 10240, al0 + ko);                                         \
    CP16(d1 + (so) + 10240, al1 + ko);                                         \
    CP16(d0 + (so) + 20480, bh0 + ko);                                         \
    CP16(d1 + (so) + 20480, bh1 + ko);                                         \
    CP16(d0 + (so) + 30720, bl0 + ko);                                         \
    CP16(d1 + (so) + 30720, bl1 + ko);                                         \
    CP_COMMIT(); }

    LDM_SETUP();
    float acc[2][8][4];
#pragma unroll
    for (int i = 0; i < 2; i++)
#pragma unroll
        for (int j = 0; j < 8; j++)
#pragma unroll
            for (int k = 0; k < 4; k++) acc[i][j][k] = 0.f;

    STAGE2(0, 0);
    const int NC = F_DIM / 32;  // 128
    for (int c = 0; c < NC; ++c) {
        const uint32_t so = (uint32_t)(c & 1) * STG_SZ;
        if (c + 1 < NC) { STAGE2(c + 1, (uint32_t)((c + 1) & 1) * STG_SZ); CP_WAIT(1); }
        else            { CP_WAIT(0); }
        __syncthreads();
        CHUNK(so);
        __syncthreads();
    }

    // epilogue: (acc + bias) * wt -> atomicAdd scatter (2 adds/elem onto 0)
    const int gid2 = lane >> 2, tg = lane & 3;
#pragma unroll
    for (int mi = 0; mi < 2; ++mi)
#pragma unroll
        for (int nt = 0; nt < 8; ++nt) {
            const int n = wn + nt * 8 + tg * 2;
            const float bv0 = bias_s[n], bv1 = bias_s[n + 1];
#pragma unroll
            for (int h = 0; h < 2; ++h) {
                const int m = wm + mi * 16 + gid2 + h * 8;
                if (m0 + m < cnt) {
                    const int   t = toks_s[m];
                    const float w = wts_s[m];
                    float* op = out + (size_t)t * D_DIM + n0 + n;
                    atomicAdd(op,     (acc[mi][nt][2 * h + 0] + bv0) * w);
                    atomicAdd(op + 1, (acc[mi][nt][2 * h + 1] + bv1) * w);
                }
            }
        }
}

// ---------------- launch -----------------------------------------------------
extern "C" void kernel_launch(void* const* d_in, const int* in_sizes, int n_in,
                              void* d_out, int out_size) {
    const float* x  = (const float*)d_in[0];
    const float* gw = (const float*)d_in[1];
    const float* w1 = (const float*)d_in[2];
    const float* b1 = (const float*)d_in[3];
    const float* w2 = (const float*)d_in[4];
    const float* b2 = (const float*)d_in[5];
    float* out   = (float*)d_out;
    float* probs = out + (size_t)T_TOK * D_DIM;

    cudaFuncSetAttribute(k_fc1_m, cudaFuncAttributeMaxDynamicSharedMemorySize, SMEM_DYN);
    cudaFuncSetAttribute(k_fc2_m, cudaFuncAttributeMaxDynamicSharedMemorySize, SMEM_DYN);

    k_init<<<512, 256>>>((float4*)out);
    k_split<<<1024, 256>>>(x, w1, w2);
    k_gate<<<T_TOK / 8, 256>>>(x, gw, probs);
    k_prefix<<<1, 32>>>();
    k_fc1_m<<<dim3(F_DIM / 128, T_TOK / 128, E_EXP), 256, SMEM_DYN>>>(b1);
    k_fc2_m<<<dim3(D_DIM / 128, T_TOK / 128, E_EXP), 256, SMEM_DYN>>>(b2, out);
}

// round 4
// speedup vs baseline: 2.6451x; 1.0681x over previous
#include <cuda_runtime.h>
#include <cuda_bf16.h>
#include <math.h>
#include <stdint.h>

#define T_TOK 8192
#define D_DIM 1024
#define F_DIM 4096
#define E_EXP 8

// ---------------- scratch (static device globals; no allocations) ----------
__device__ int   g_cnt[E_EXP];
__device__ int   g_off[E_EXP];
__device__ int   g_tok[E_EXP * T_TOK];
__device__ float g_wt [E_EXP * T_TOK];

__device__ __nv_bfloat16 g_xhi [(size_t)T_TOK * D_DIM];
__device__ __nv_bfloat16 g_xlo [(size_t)T_TOK * D_DIM];
__device__ __nv_bfloat16 g_w1hi[(size_t)E_EXP * F_DIM * D_DIM];
__device__ __nv_bfloat16 g_w1lo[(size_t)E_EXP * F_DIM * D_DIM];
__device__ __nv_bfloat16 g_w2hi[(size_t)E_EXP * D_DIM * F_DIM];
__device__ __nv_bfloat16 g_w2lo[(size_t)E_EXP * D_DIM * F_DIM];
__device__ __nv_bfloat16 g_hhi [(size_t)2 * T_TOK * F_DIM];
__device__ __nv_bfloat16 g_hlo [(size_t)2 * T_TOK * F_DIM];

// ---------------- PTX helpers (sm_80+ features only; no 'a'-gated ops) -----
__device__ __forceinline__ uint32_t smem_u32(const void* p) {
    uint32_t a;
    asm("{ .reg .u64 t; cvta.to.shared.u64 t, %1; cvt.u32.u64 %0, t; }" : "=r"(a) : "l"(p));
    return a;
}
#define CP16(dst, src) asm volatile("cp.async.cg.shared.global [%0], [%1], 16;" :: "r"(dst), "l"(src) : "memory")
#define CP_COMMIT()    asm volatile("cp.async.commit_group;" ::: "memory")
#define CP_WAIT(n)     asm volatile("cp.async.wait_group %0;" :: "n"(n) : "memory")
#define LDX4(r, a)                                                             \
    asm volatile("ldmatrix.sync.aligned.m8n8.x4.shared.b16 {%0,%1,%2,%3}, [%4];" \
        : "=r"((r)[0]), "=r"((r)[1]), "=r"((r)[2]), "=r"((r)[3]) : "r"(a))
#define MMA16(d, a, b0, b1)                                                    \
    asm volatile("mma.sync.aligned.m16n8k16.row.col.f32.bf16.bf16.f32 "        \
        "{%0,%1,%2,%3},{%4,%5,%6,%7},{%8,%9},{%0,%1,%2,%3};"                   \
        : "+f"((d)[0]), "+f"((d)[1]), "+f"((d)[2]), "+f"((d)[3])               \
        : "r"((a)[0]), "r"((a)[1]), "r"((a)[2]), "r"((a)[3]), "r"(b0), "r"(b1))

__device__ __forceinline__ uint32_t pack_bf(__nv_bfloat16 a, __nv_bfloat16 b) {
    return ((uint32_t)__bfloat16_as_ushort(b) << 16) | __bfloat16_as_ushort(a);
}

// SMEM: [0,512) toks, [512,1024) bias, [1024,1536) wts, [2048, 2048+2*40960) stages
// stage layout: Ahi @0, Alo @10240, Bhi @20480, Blo @30720; row pitch 80B (32 bf16 + pad)
#define SM_STAGE 2048
#define STG_SZ   40960
#define SMEM_DYN (SM_STAGE + 2 * STG_SZ)

// ---------------- init ------------------------------------------------------
__global__ void k_init(float4* __restrict__ out4) {
    int i = blockIdx.x * blockDim.x + threadIdx.x;
    if (i < E_EXP) g_cnt[i] = 0;
    const size_t n4 = (size_t)T_TOK * D_DIM / 4;
    float4 z = make_float4(0.f, 0.f, 0.f, 0.f);
    for (size_t j = i; j < n4; j += (size_t)gridDim.x * blockDim.x) out4[j] = z;
}

// ---------------- split fp32 -> bf16 hi/lo ----------------------------------
__device__ __forceinline__ void split4(__nv_bfloat16* hi, __nv_bfloat16* lo,
                                       const float* s, size_t i) {
    float4 f = ((const float4*)s)[i];
    __nv_bfloat16 h0 = __float2bfloat16(f.x), h1 = __float2bfloat16(f.y);
    __nv_bfloat16 h2 = __float2bfloat16(f.z), h3 = __float2bfloat16(f.w);
    __nv_bfloat16 l0 = __float2bfloat16(f.x - __bfloat162float(h0));
    __nv_bfloat16 l1 = __float2bfloat16(f.y - __bfloat162float(h1));
    __nv_bfloat16 l2 = __float2bfloat16(f.z - __bfloat162float(h2));
    __nv_bfloat16 l3 = __float2bfloat16(f.w - __bfloat162float(h3));
    ((uint2*)hi)[i] = make_uint2(pack_bf(h0, h1), pack_bf(h2, h3));
    ((uint2*)lo)[i] = make_uint2(pack_bf(l0, l1), pack_bf(l2, l3));
}
__global__ void k_split(const float* __restrict__ x, const float* __restrict__ w1,
                        const float* __restrict__ w2) {
    size_t stride = (size_t)gridDim.x * blockDim.x;
    size_t i0 = (size_t)blockIdx.x * blockDim.x + threadIdx.x;
    const size_t nx4 = (size_t)T_TOK * D_DIM / 4;
    const size_t nw4 = (size_t)E_EXP * F_DIM * D_DIM / 4;
    for (size_t i = i0; i < nx4; i += stride) split4(g_xhi, g_xlo, x, i);
    for (size_t i = i0; i < nw4; i += stride) split4(g_w1hi, g_w1lo, w1, i);
    for (size_t i = i0; i < nw4; i += stride) split4(g_w2hi, g_w2lo, w2, i);
}

// ---------------- gating (validated in R1) ----------------------------------
__global__ void k_gate(const float* __restrict__ x, const float* __restrict__ gw,
                       float* __restrict__ probs_out) {
    int warp = (blockIdx.x * blockDim.x + threadIdx.x) >> 5;
    int lane = threadIdx.x & 31;
    if (warp >= T_TOK) return;
    const float* xr = x + (size_t)warp * D_DIM;
    float acc[E_EXP];
#pragma unroll
    for (int e = 0; e < E_EXP; e++) acc[e] = 0.f;
    for (int k = lane * 4; k < D_DIM; k += 128) {
        float4 xv = *(const float4*)(xr + k);
#pragma unroll
        for (int e = 0; e < E_EXP; e++) {
            float4 wv = *(const float4*)(gw + (size_t)e * D_DIM + k);
            acc[e] += xv.x * wv.x + xv.y * wv.y + xv.z * wv.z + xv.w * wv.w;
        }
    }
#pragma unroll
    for (int e = 0; e < E_EXP; e++)
#pragma unroll
        for (int o = 16; o > 0; o >>= 1) acc[e] += __shfl_xor_sync(0xffffffffu, acc[e], o);
    if (lane == 0) {
        float mx = acc[0];
#pragma unroll
        for (int e = 1; e < E_EXP; e++) mx = fmaxf(mx, acc[e]);
        float p[E_EXP], s = 0.f;
#pragma unroll
        for (int e = 0; e < E_EXP; e++) { p[e] = expf(acc[e] - mx); s += p[e]; }
        float inv = 1.f / s;
#pragma unroll
        for (int e = 0; e < E_EXP; e++) {
            p[e] *= inv;
            probs_out[(size_t)warp * E_EXP + e] = p[e];
        }
        int i0 = 0;
#pragma unroll
        for (int e = 1; e < E_EXP; e++) if (p[e] > p[i0]) i0 = e;
        int i1 = (i0 == 0) ? 1 : 0;
#pragma unroll
        for (int e = 0; e < E_EXP; e++) if (e != i0 && p[e] > p[i1]) i1 = e;
        float denom = p[i0] + p[i1] + 1e-9f;
        int s0 = atomicAdd(&g_cnt[i0], 1);
        g_tok[i0 * T_TOK + s0] = warp; g_wt[i0 * T_TOK + s0] = p[i0] / denom;
        int s1 = atomicAdd(&g_cnt[i1], 1);
        g_tok[i1 * T_TOK + s1] = warp; g_wt[i1 * T_TOK + s1] = p[i1] / denom;
    }
}
__global__ void k_prefix() {
    if (threadIdx.x == 0) {
        int run = 0;
#pragma unroll
        for (int e = 0; e < E_EXP; e++) { g_off[e] = run; run += g_cnt[e]; }
    }
}

// ---------------- shared GEMM chunk: 128x128x32, 3-term bf16 split ----------
// MMA order: per B-group issue hh x4 (distinct accs), then hl x4, then lh x4.
// Per-accumulator addition order unchanged (hh, hl, lh) => identical numerics,
// but consecutive instructions never share an accumulator (hides HMMA latency).
#define CHUNK(so)                                                              \
    _Pragma("unroll") for (int kk = 0; kk < 2; ++kk) {                         \
        uint32_t Ah0[4], Ah1[4], Al0[4], Al1[4];                               \
        LDX4(Ah0, aa0 + (so) + kk * 32);                                       \
        LDX4(Ah1, aa1 + (so) + kk * 32);                                       \
        LDX4(Al0, aa0 + (so) + 10240 + kk * 32);                               \
        LDX4(Al1, aa1 + (so) + 10240 + kk * 32);                               \
        _Pragma("unroll") for (int g = 0; g < 4; ++g) {                        \
            uint32_t Bh[4], Bl[4];                                             \
            LDX4(Bh, bbv[g] + (so) + kk * 32);                                 \
            LDX4(Bl, bbv[g] + (so) + 10240 + kk * 32);                         \
            MMA16(acc[0][2 * g],     Ah0, Bh[0], Bh[1]);                       \
            MMA16(acc[1][2 * g],     Ah1, Bh[0], Bh[1]);                       \
            MMA16(acc[0][2 * g + 1], Ah0, Bh[2], Bh[3]);                       \
            MMA16(acc[1][2 * g + 1], Ah1, Bh[2], Bh[3]);                       \
            MMA16(acc[0][2 * g],     Ah0, Bl[0], Bl[1]);                       \
            MMA16(acc[1][2 * g],     Ah1, Bl[0], Bl[1]);                       \
            MMA16(acc[0][2 * g + 1], Ah0, Bl[2], Bl[3]);                       \
            MMA16(acc[1][2 * g + 1], Ah1, Bl[2], Bl[3]);                       \
            MMA16(acc[0][2 * g],     Al0, Bh[0], Bh[1]);                       \
            MMA16(acc[1][2 * g],     Al1, Bh[0], Bh[1]);                       \
            MMA16(acc[0][2 * g + 1], Al0, Bh[2], Bh[3]);                       \
            MMA16(acc[1][2 * g + 1], Al1, Bh[2], Bh[3]);                       \
        }                                                                      \
    }

#define LDM_SETUP()                                                            \
    const int lane = tid & 31, wid = tid >> 5;                                 \
    const int wm = (wid & 3) * 32, wn = (wid >> 2) * 64;                       \
    const uint32_t aa0 = sb + SM_STAGE +                                       \
        (wm + (lane & 7) + ((lane >> 3) & 1) * 8) * 80 + ((lane >> 4) & 1) * 16; \
    const uint32_t aa1 = aa0 + 16 * 80;                                        \
    uint32_t bbv[4];                                                           \
    _Pragma("unroll") for (int g = 0; g < 4; ++g)                              \
        bbv[g] = sb + SM_STAGE + 20480 +                                       \
            (wn + g * 16 + (lane & 7) + ((lane >> 4) & 1) * 8) * 80 +          \
            ((lane >> 3) & 1) * 16;

// ---------------- fc1: h = gelu(X[gather] @ W1e^T + b1) -> bf16 hi/lo -------
__global__ __launch_bounds__(256, 2) void k_fc1_m(const float* __restrict__ b1) {
    const int e = blockIdx.z;
    const int cnt = g_cnt[e];
    const int m0 = blockIdx.y * 128;
    if (m0 >= cnt) return;
    const int n0 = blockIdx.x * 128;

    extern __shared__ __align__(128) char smp[];
    const uint32_t sb = smem_u32(smp);
    int*   toks_s = (int*)smp;
    float* bias_s = (float*)(smp + 512);
    const int tid = threadIdx.x;
    if (tid < 128) {
        toks_s[tid] = g_tok[e * T_TOK + min(m0 + tid, cnt - 1)];
        bias_s[tid] = b1[e * F_DIM + n0 + tid];
    }
    __syncthreads();

    // staging: thread -> quad q, rows r0 / r0+64 of each of 4 arrays
    const int q = tid & 3, r0 = tid >> 2, r1 = r0 + 64;
    const uint32_t d0 = sb + SM_STAGE + r0 * 80 + q * 16;
    const uint32_t d1 = sb + SM_STAGE + r1 * 80 + q * 16;
    const uint32_t a0off = (uint32_t)toks_s[r0] * (D_DIM * 2) + q * 16;
    const uint32_t a1off = (uint32_t)toks_s[r1] * (D_DIM * 2) + q * 16;
    const char* xhi = (const char*)g_xhi;
    const char* xlo = (const char*)g_xlo;
    const char* bh0 = (const char*)(g_w1hi + ((size_t)e * F_DIM + n0 + r0) * D_DIM) + q * 16;
    const char* bh1 = (const char*)(g_w1hi + ((size_t)e * F_DIM + n0 + r1) * D_DIM) + q * 16;
    const char* bl0 = (const char*)(g_w1lo + ((size_t)e * F_DIM + n0 + r0) * D_DIM) + q * 16;
    const char* bl1 = (const char*)(g_w1lo + ((size_t)e * F_DIM + n0 + r1) * D_DIM) + q * 16;

#define STAGE1(c, so) { const uint32_t ko = (uint32_t)(c) * 64;                \
    CP16(d0 + (so),         xhi + a0off + ko);                                 \
    CP16(d1 + (so),         xhi + a1off + ko);                                 \
    CP16(d0 + (so) + 10240, xlo + a0off + ko);                                 \
    CP16(d1 + (so) + 10240, xlo + a1off + ko);                                 \
    CP16(d0 + (so) + 20480, bh0 + ko);                                         \
    CP16(d1 + (so) + 20480, bh1 + ko);                                         \
    CP16(d0 + (so) + 30720, bl0 + ko);                                         \
    CP16(d1 + (so) + 30720, bl1 + ko);                                         \
    CP_COMMIT(); }

    LDM_SETUP();
    float acc[2][8][4];
#pragma unroll
    for (int i = 0; i < 2; i++)
#pragma unroll
        for (int j = 0; j < 8; j++)
#pragma unroll
            for (int k = 0; k < 4; k++) acc[i][j][k] = 0.f;

    STAGE1(0, 0);
    const int NC = D_DIM / 32;  // 32
    for (int c = 0; c < NC; ++c) {
        const uint32_t so = (uint32_t)(c & 1) * STG_SZ;
        if (c + 1 < NC) { STAGE1(c + 1, (uint32_t)((c + 1) & 1) * STG_SZ); CP_WAIT(1); }
        else            { CP_WAIT(0); }
        __syncthreads();
        CHUNK(so);
        __syncthreads();
    }

    // epilogue: bias + exact gelu -> split bf16 -> g_hhi/g_hlo
    const int gid2 = lane >> 2, tg = lane & 3;
    const int hbase = g_off[e] + m0;
    uint32_t* ghi = (uint32_t*)g_hhi;
    uint32_t* glo = (uint32_t*)g_hlo;
#pragma unroll
    for (int mi = 0; mi < 2; ++mi)
#pragma unroll
        for (int nt = 0; nt < 8; ++nt) {
            const int n = wn + nt * 8 + tg * 2;
            const float bv0 = bias_s[n], bv1 = bias_s[n + 1];
#pragma unroll
            for (int h = 0; h < 2; ++h) {
                const int m = wm + mi * 16 + gid2 + h * 8;
                if (m0 + m < cnt) {
                    float v0 = acc[mi][nt][2 * h + 0] + bv0;
                    float v1 = acc[mi][nt][2 * h + 1] + bv1;
                    v0 = 0.5f * v0 * (1.f + erff(v0 * 0.7071067811865476f));
                    v1 = 0.5f * v1 * (1.f + erff(v1 * 0.7071067811865476f));
                    __nv_bfloat16 h0 = __float2bfloat16(v0), h1 = __float2bfloat16(v1);
                    __nv_bfloat16 l0 = __float2bfloat16(v0 - __bfloat162float(h0));
                    __nv_bfloat16 l1 = __float2bfloat16(v1 - __bfloat162float(h1));
                    size_t idx = (size_t)(hbase + m) * (F_DIM / 2) + (size_t)(n0 + n) / 2;
                    ghi[idx] = pack_bf(h0, h1);
                    glo[idx] = pack_bf(l0, l1);
                }
            }
        }
}

// ---------------- fc2: out[tok] += w * (h @ W2e^T + b2) ---------------------
__global__ __launch_bounds__(256, 2) void k_fc2_m(const float* __restrict__ b2,
                                                  float* __restrict__ out) {
    const int e = blockIdx.z;
    const int cnt = g_cnt[e];
    const int m0 = blockIdx.y * 128;
    if (m0 >= cnt) return;
    const int n0 = blockIdx.x * 128;

    extern __shared__ __align__(128) char smp[];
    const uint32_t sb = smem_u32(smp);
    int*   toks_s = (int*)smp;
    float* bias_s = (float*)(smp + 512);
    float* wts_s  = (float*)(smp + 1024);
    const int tid = threadIdx.x;
    if (tid < 128) {
        const int slot = min(m0 + tid, cnt - 1);
        toks_s[tid] = g_tok[e * T_TOK + slot];
        wts_s[tid]  = g_wt [e * T_TOK + slot];
        bias_s[tid] = b2[e * D_DIM + n0 + tid];
    }
    __syncthreads();

    const int q = tid & 3, r0 = tid >> 2, r1 = r0 + 64;
    const uint32_t d0 = sb + SM_STAGE + r0 * 80 + q * 16;
    const uint32_t d1 = sb + SM_STAGE + r1 * 80 + q * 16;
    const uint32_t slot0 = (uint32_t)(g_off[e] + min(m0 + r0, cnt - 1));
    const uint32_t slot1 = (uint32_t)(g_off[e] + min(m0 + r1, cnt - 1));
    const char* ah0 = (const char*)(g_hhi + (size_t)slot0 * F_DIM) + q * 16;
    const char* ah1 = (const char*)(g_hhi + (size_t)slot1 * F_DIM) + q * 16;
    const char* al0 = (const char*)(g_hlo + (size_t)slot0 * F_DIM) + q * 16;
    const char* al1 = (const char*)(g_hlo + (size_t)slot1 * F_DIM) + q * 16;
    const char* bh0 = (const char*)(g_w2hi + ((size_t)e * D_DIM + n0 + r0) * F_DIM) + q * 16;
    const char* bh1 = (const char*)(g_w2hi + ((size_t)e * D_DIM + n0 + r1) * F_DIM) + q * 16;
    const char* bl0 = (const char*)(g_w2lo + ((size_t)e * D_DIM + n0 + r0) * F_DIM) + q * 16;
    const char* bl1 = (const char*)(g_w2lo + ((size_t)e * D_DIM + n0 + r1) * F_DIM) + q * 16;

#define STAGE2(c, so) { const uint32_t ko = (uint32_t)(c) * 64;                \
    CP16(d0 + (so),         ah0 + ko);                                         \
    CP16(d1 + (so),         ah1 + ko);                                         \
    CP16(d0 + (so) + 10240, al0 + ko);                                         \
    CP16(d1 + (so) + 10240, al1 + ko);                                         \
    CP16(d0 + (so) + 20480, bh0 + ko);                                         \
    CP16(d1 + (so) + 20480, bh1 + ko);                                         \
    CP16(d0 + (so) + 30720, bl0 + ko);                                         \
    CP16(d1 + (so) + 30720, bl1 + ko);                                         \
    CP_COMMIT(); }

    LDM_SETUP();
    float acc[2][8][4];
#pragma unroll
    for (int i = 0; i < 2; i++)
#pragma unroll
        for (int j = 0; j < 8; j++)
#pragma unroll
            for (int k = 0; k < 4; k++) acc[i][j][k] = 0.f;

    STAGE2(0, 0);
    const int NC = F_DIM / 32;  // 128
    for (int c = 0; c < NC; ++c) {
        const uint32_t so = (uint32_t)(c & 1) * STG_SZ;
        if (c + 1 < NC) { STAGE2(c + 1, (uint32_t)((c + 1) & 1) * STG_SZ); CP_WAIT(1); }
        else            { CP_WAIT(0); }
        __syncthreads();
        CHUNK(so);
        __syncthreads();
    }

    // epilogue: (acc + bias) * wt -> atomicAdd scatter (2 adds/elem onto 0)
    const int gid2 = lane >> 2, tg = lane & 3;
#pragma unroll
    for (int mi = 0; mi < 2; ++mi)
#pragma unroll
        for (int nt = 0; nt < 8; ++nt) {
            const int n = wn + nt * 8 + tg * 2;
            const float bv0 = bias_s[n], bv1 = bias_s[n + 1];
#pragma unroll
            for (int h = 0; h < 2; ++h) {
                const int m = wm + mi * 16 + gid2 + h * 8;
                if (m0 + m < cnt) {
                    const int   t = toks_s[m];
                    const float w = wts_s[m];
                    float* op = out + (size_t)t * D_DIM + n0 + n;
                    atomicAdd(op,     (acc[mi][nt][2 * h + 0] + bv0) * w);
                    atomicAdd(op + 1, (acc[mi][nt][2 * h + 1] + bv1) * w);
                }
            }
        }
}

// ---------------- launch -----------------------------------------------------
extern "C" void kernel_launch(void* const* d_in, const int* in_sizes, int n_in,
                              void* d_out, int out_size) {
    const float* x  = (const float*)d_in[0];
    const float* gw = (const float*)d_in[1];
    const float* w1 = (const float*)d_in[2];
    const float* b1 = (const float*)d_in[3];
    const float* w2 = (const float*)d_in[4];
    const float* b2 = (const float*)d_in[5];
    float* out   = (float*)d_out;
    float* probs = out + (size_t)T_TOK * D_DIM;

    cudaFuncSetAttribute(k_fc1_m, cudaFuncAttributeMaxDynamicSharedMemorySize, SMEM_DYN);
    cudaFuncSetAttribute(k_fc2_m, cudaFuncAttributeMaxDynamicSharedMemorySize, SMEM_DYN);

    k_init<<<512, 256>>>((float4*)out);
    k_split<<<1024, 256>>>(x, w1, w2);
    k_gate<<<T_TOK / 8, 256>>>(x, gw, probs);
    k_prefix<<<1, 32>>>();
    k_fc1_m<<<dim3(F_DIM / 128, T_TOK / 128, E_EXP), 256, SMEM_DYN>>>(b1);
    k_fc2_m<<<dim3(D_DIM / 128, T_TOK / 128, E_EXP), 256, SMEM_DYN>>>(b2, out);
}